// round 15
// baseline (speedup 1.0000x reference)
#include <cuda_runtime.h>
#include <cuda_bf16.h>
#include <cstdint>

// GroupEmbedding: out[b,g,d] = sum_f x[b, group_idx[g,f]] * W[g,f,d] + bias[g,d]
// zeroed where masked_group_idx[b] == g.
// B=8192, NF=128, G=16, F=8, D=512. 256 MB output.
//
// R12/R14: kernel is FFMA-ISSUE-bound (92 issue-cyc per 512B warp-row ≈ measured 45us).
//      Halve the FMA instruction stream with Blackwell packed fma.rn.f32x2:
//      x pre-duplicated as (v,v) float2 in shared -> LDS.64 gives ready f32x2
//      multiplier; 16 FFMA2 instead of 32 FFMA per row. ~60 cyc/row -> DRAM-bound.
//      (R14 = R12 resubmit: previous bench was an infra failure, kernel never ran.)

#define B_TOTAL  8192
#define NF_      128
#define G_       16
#define F_       8
#define D_       512
#define D4_      (D_ / 4)            // 128 float4 per (b,g)
#define CHUNK    16                  // rows per chunk
#define NCHUNKS  (B_TOTAL / CHUNK)   // 512 chunks per group
#define JSTRIDE  74                  // blocks per group: 16*74 = 1184 = one wave
#define NTHREADS 128                 // one thread per d4 column

typedef unsigned long long ull;

#define FMA_F32X2(d, a, b, c) \
    asm("fma.rn.f32x2 %0, %1, %2, %3;" : "=l"(d) : "l"(a), "l"(b), "l"(c))

__global__ __launch_bounds__(NTHREADS, 8)
void group_embedding_kernel(const float* __restrict__ x,
                            const float* __restrict__ W,
                            const float* __restrict__ bias,
                            const int*   __restrict__ gidx_raw,   // int32 view; may be int64
                            const int*   __restrict__ mgi_raw,    // int32 view; may be int64
                            float*       __restrict__ out)
{
    const int bx = blockIdx.x;
    const int g  = bx & 15;             // group: constant for this block
    const int j  = bx >> 4;             // 0..73, chunk stripe
    const int t  = threadIdx.x;         // 0..127 -> d4 column

    __shared__ ull xs2[CHUNK][F_];      // (v,v) duplicated pairs; broadcast-read
    __shared__ int msk[CHUNK];
    __shared__ int cols[F_];
    __shared__ int flags;               // bit0: gidx is int32; bit1: mgi is int32

    // --- dtype detection: int64 LE values (<128) have all-zero odd 32-bit words ---
    if (t < 32) {
        int pg = gidx_raw[2 * t + 1];
        int pm = mgi_raw[2 * t + 1];
        int gi32 = __any_sync(0xffffffffu, pg != 0);
        int mi32 = __any_sync(0xffffffffu, pm != 0);
        if (t == 0) flags = (gi32 ? 1 : 0) | (mi32 ? 2 : 0);
    }
    __syncthreads();
    const bool gidx_i32 = (flags & 1) != 0;
    const bool mgi_i32  = (flags & 2) != 0;

    if (t < F_) {
        int idx = g * F_ + t;
        cols[t] = gidx_i32 ? gidx_raw[idx] : gidx_raw[2 * idx];
    }
    __syncthreads();

    // --- W column (8 float4 -> 16 b64 pairs) + bias into registers; reused for all chunks ---
    const float4* __restrict__ W4 = (const float4*)W;
    ull w01[F_], w23[F_];
#pragma unroll
    for (int f = 0; f < F_; f++) {
        float4 wf = W4[(g * F_ + f) * D4_ + t];
        w01[f] = ((const ull*)&wf)[0];
        w23[f] = ((const ull*)&wf)[1];
    }
    float4 bb = ((const float4*)bias)[g * D4_ + t];
    const ull bb01 = ((const ull*)&bb)[0];
    const ull bb23 = ((const ull*)&bb)[1];

    const int ROWSTRIDE = G_ * D4_;     // float4 units between consecutive b rows
    float4* __restrict__ out4 = (float4*)out;

    // --- persistent loop over this block's chunks (6-7 per block, 68/74 do 7) ---
    for (int cb = j; cb < NCHUNKS; cb += JSTRIDE) {
        const int b0 = cb * CHUNK;

        // gather x tile, storing duplicated (v,v) pairs (t*8B consecutive: conflict-free)
        {
            int r = t >> 3, f = t & 7;
            float v = x[(b0 + r) * NF_ + cols[f]];
            float2 vv = make_float2(v, v);
            xs2[r][f] = *(const ull*)&vv;
            if (t < CHUNK)
                msk[t] = mgi_i32 ? mgi_raw[b0 + t] : mgi_raw[2 * (b0 + t)];
        }
        __syncthreads();

        float4* __restrict__ p = out4 + ((size_t)b0 * G_ + (size_t)g) * D4_ + t;
#pragma unroll
        for (int r = 0; r < CHUNK; r++) {
            ull a01 = bb01, a23 = bb23;
#pragma unroll
            for (int f = 0; f < F_; f++) {
                const ull xv = xs2[r][f];          // LDS.64 broadcast: (x, x)
                FMA_F32X2(a01, xv, w01[f], a01);   // 2 MACs / instruction
                FMA_F32X2(a23, xv, w23[f], a23);
            }
            if (msk[r] == g) { a01 = 0ull; a23 = 0ull; }
            float4 o;
            ((ull*)&o)[0] = a01;
            ((ull*)&o)[1] = a23;
            p[0] = o;                              // plain coalesced STG.128
            p += ROWSTRIDE;
        }
        __syncthreads();                           // protect xs2/msk before next gather
    }
}

extern "C" void kernel_launch(void* const* d_in, const int* in_sizes, int n_in,
                              void* d_out, int out_size)
{
    const float* x    = (const float*)d_in[0];
    const float* W    = (const float*)d_in[1];
    const float* bias = (const float*)d_in[2];
    const int*   gidx = (const int*)d_in[3];
    const int*   mgi  = (const int*)d_in[4];
    float*       out  = (float*)d_out;

    group_embedding_kernel<<<G_ * JSTRIDE, NTHREADS>>>(x, W, bias, gidx, mgi, out);
}